// round 6
// baseline (speedup 1.0000x reference)
#include <cuda_runtime.h>
#include <cstdint>

typedef unsigned long long ull;

#define BB   128
#define TT   512
#define FF   128
#define UU   512
#define G3   1536
#define NCTA 128
#define NTHR 256
#define KC   32

#define AREG 260          // floats per bg region in act buffer (KC*8 + 4 pad)
#define ABUF (8 * AREG)   // 2080 floats per act buffer
#define NBUF 4            // pipeline depth

// SMEM float offsets
#define OFF_W1X 0          // 128*24  = 3072
#define OFF_U1  3072       // 512*24  = 12288
#define OFF_W2  15360      // 512*24  = 12288
#define OFF_U2  27648      // 512*24  = 12288
#define OFF_ACT 39936      // 4*2080  = 8320
#define OFF_RED 48256      // 3072 ull = 6144 floats (shared L1/L2 phases)
#define SMEM_FLOATS 54400  // 217600 bytes

// ---------------- static device scratch ----------------
__device__ __align__(128) float g_xT[(size_t)TT * FF * BB];  // (T, F, B)
__device__ __align__(128) float g_h1[2 * UU * BB];
__device__ __align__(128) float g_h2[2 * UU * BB];
__device__ __align__(128) int   g_bar[TT + 2];               // per-step counters

// ---------------- helpers ----------------
__device__ __forceinline__ ull fma2(ull a, ull b, ull c) {
    ull d; asm("fma.rn.f32x2 %0, %1, %2, %3;" : "=l"(d) : "l"(a), "l"(b), "l"(c)); return d;
}
__device__ __forceinline__ ull add2(ull a, ull b) {
    ull d; asm("add.rn.f32x2 %0, %1, %2;" : "=l"(d) : "l"(a), "l"(b)); return d;
}
__device__ __forceinline__ ull pack2(float f) {
    ull d; asm("mov.b64 %0, {%1, %1};" : "=l"(d) : "f"(f)); return d;
}
__device__ __forceinline__ float2 asf2(ull v) {
    float2 f; asm("mov.b64 {%0, %1}, %2;" : "=f"(f.x), "=f"(f.y) : "l"(v)); return f;
}
__device__ __forceinline__ float sigm(float v) { return 1.0f / (1.0f + __expf(-v)); }

// R4-proven grid barrier: contention-light arrival, single-thread acquire poll
__device__ __forceinline__ void grid_barrier(int* bar) {
    __syncthreads();
    if (threadIdx.x == 0) {
        asm volatile("red.release.gpu.global.add.u32 [%0], 1;" :: "l"(bar) : "memory");
        int v;
        do {
            asm volatile("ld.acquire.gpu.global.u32 %0, [%1];" : "=r"(v) : "l"(bar) : "memory");
        } while (v < NCTA);
    }
    __syncthreads();
}

// global weight slab -> smem [k][u*3+g], cols g*512 + ug*8 + u
__device__ void load_w(float* dst, const float* src, int R, int ug, int tid) {
    for (int idx = tid; idx < R * 24; idx += NTHR) {
        int k = idx / 24, c = idx - k * 24;
        int u = c / 3, g = c - u * 3;
        dst[idx] = src[(size_t)k * G3 + g * UU + ug * 8 + u];
    }
}

// stream one KC x 64-batch chunk: 2048 floats = 512 float4 -> 2 per thread
__device__ __forceinline__ void cp_chunk(float* dstbuf, const float* src, int tid) {
    uint32_t d0 = (uint32_t)__cvta_generic_to_shared(dstbuf);
    #pragma unroll
    for (int i = 0; i < 2; i++) {
        int f = tid + NTHR * i;           // 0..511
        int k = f >> 4, seg = f & 15;
        int bgr = seg >> 1, half = seg & 1;
        uint32_t da = d0 + (uint32_t)((bgr * AREG + k * 8 + half * 4) * 4);
        const float* s = src + (size_t)k * BB + seg * 4;
        asm volatile("cp.async.cg.shared.global [%0], [%1], 16;" :: "r"(da), "l"(s) : "memory");
    }
    asm volatile("cp.async.commit_group;" ::: "memory");
}
__device__ __forceinline__ void cp_commit_empty() {
    asm volatile("cp.async.commit_group;" ::: "memory");
}
__device__ __forceinline__ void cp_wait2() {
    asm volatile("cp.async.wait_group 2;" ::: "memory");
}

// single-layer chunk: 12 FMA2 per k
__device__ __forceinline__ void cc1(const float* A, const float* w, int kg, int unit, int bg,
                                    ull* az, ull* ar, ull* ah) {
    #pragma unroll
    for (int i = 0; i < KC / 4; i++) {
        int k = 4 * i + kg;
        const float* ap = A + bg * AREG + k * 8;
        ulonglong2 p01 = *reinterpret_cast<const ulonglong2*>(ap);
        ulonglong2 p23 = *reinterpret_cast<const ulonglong2*>(ap + 4);
        const float* wp = w + k * 24 + unit * 3;
        ull wz = pack2(wp[0]), wr = pack2(wp[1]), wh = pack2(wp[2]);
        az[0] = fma2(p01.x, wz, az[0]); az[1] = fma2(p01.y, wz, az[1]);
        az[2] = fma2(p23.x, wz, az[2]); az[3] = fma2(p23.y, wz, az[3]);
        ar[0] = fma2(p01.x, wr, ar[0]); ar[1] = fma2(p01.y, wr, ar[1]);
        ar[2] = fma2(p23.x, wr, ar[2]); ar[3] = fma2(p23.y, wr, ar[3]);
        ah[0] = fma2(p01.x, wh, ah[0]); ah[1] = fma2(p01.y, wh, ah[1]);
        ah[2] = fma2(p23.x, wh, ah[2]); ah[3] = fma2(p23.y, wh, ah[3]);
    }
}

// dual-layer chunk over h1 rows: acts read once, 24 FMA2 per k
__device__ __forceinline__ void cc2(const float* A, const float* wa, const float* wb,
                                    int kg, int unit, int bg,
                                    ull* az1, ull* ar1, ull* ah1,
                                    ull* az2, ull* ar2, ull* ah2) {
    #pragma unroll
    for (int i = 0; i < KC / 4; i++) {
        int k = 4 * i + kg;
        const float* ap = A + bg * AREG + k * 8;
        ulonglong2 p01 = *reinterpret_cast<const ulonglong2*>(ap);
        ulonglong2 p23 = *reinterpret_cast<const ulonglong2*>(ap + 4);
        const float* wpa = wa + k * 24 + unit * 3;
        const float* wpb = wb + k * 24 + unit * 3;
        ull za = pack2(wpa[0]), ra = pack2(wpa[1]), ha = pack2(wpa[2]);
        ull zb = pack2(wpb[0]), rb = pack2(wpb[1]), hb = pack2(wpb[2]);
        az1[0] = fma2(p01.x, za, az1[0]); az1[1] = fma2(p01.y, za, az1[1]);
        az1[2] = fma2(p23.x, za, az1[2]); az1[3] = fma2(p23.y, za, az1[3]);
        ar1[0] = fma2(p01.x, ra, ar1[0]); ar1[1] = fma2(p01.y, ra, ar1[1]);
        ar1[2] = fma2(p23.x, ra, ar1[2]); ar1[3] = fma2(p23.y, ra, ar1[3]);
        ah1[0] = fma2(p01.x, ha, ah1[0]); ah1[1] = fma2(p01.y, ha, ah1[1]);
        ah1[2] = fma2(p23.x, ha, ah1[2]); ah1[3] = fma2(p23.y, ha, ah1[3]);
        az2[0] = fma2(p01.x, zb, az2[0]); az2[1] = fma2(p01.y, zb, az2[1]);
        az2[2] = fma2(p23.x, zb, az2[2]); az2[3] = fma2(p23.y, zb, az2[3]);
        ar2[0] = fma2(p01.x, rb, ar2[0]); ar2[1] = fma2(p01.y, rb, ar2[1]);
        ar2[2] = fma2(p23.x, rb, ar2[2]); ar2[3] = fma2(p23.y, rb, ar2[3]);
        ah2[0] = fma2(p01.x, hb, ah2[0]); ah2[1] = fma2(p01.y, hb, ah2[1]);
        ah2[2] = fma2(p23.x, hb, ah2[2]); ah2[3] = fma2(p23.y, hb, ah2[3]);
    }
}

__device__ __forceinline__ void red_store(ull* base, ull* z, ull* r, ull* hx, ull* hr) {
    #pragma unroll
    for (int p = 0; p < 4; p++) {
        base[p * 64]        = z[p];
        base[(4 + p) * 64]  = r[p];
        base[(8 + p) * 64]  = hx[p];
        base[(12 + p) * 64] = hr[p];
    }
}
__device__ __forceinline__ void red_accum(const ull* redb, int slot,
                                          ull* z, ull* r, ull* hx, ull* hr) {
    #pragma unroll
    for (int s = 0; s < 3; s++) {
        const ull* base = redb + (size_t)s * 16 * 64 + slot;
        #pragma unroll
        for (int p = 0; p < 4; p++) {
            z[p]  = add2(z[p],  base[p * 64]);
            r[p]  = add2(r[p],  base[(4 + p) * 64]);
            hx[p] = add2(hx[p], base[(8 + p) * 64]);
            hr[p] = add2(hr[p], base[(12 + p) * 64]);
        }
    }
}

__device__ __forceinline__ void finalize(const float* hprev, float* hnext,
                                         int j, int bbase,
                                         ull* z, ull* r, ull* hx, ull* hr,
                                         float bZ, float bR, float bHx, float bHr) {
    const float* hp = hprev + (size_t)j * BB + bbase;
    float4 h0 = __ldcg((const float4*)hp);
    float4 h1 = __ldcg((const float4*)(hp + 4));
    float hpv[8] = {h0.x, h0.y, h0.z, h0.w, h1.x, h1.y, h1.z, h1.w};
    float hn[8];
    #pragma unroll
    for (int p = 0; p < 4; p++) {
        float2 zz = asf2(z[p]), rr = asf2(r[p]), xx = asf2(hx[p]), hh = asf2(hr[p]);
        float zv = sigm(zz.x + bZ);
        float rv = sigm(rr.x + bR);
        float cand = fmaxf(xx.x + bHx + rv * (hh.x + bHr), 0.0f);
        hn[2 * p] = zv * hpv[2 * p] + (1.0f - zv) * cand;
        zv = sigm(zz.y + bZ);
        rv = sigm(rr.y + bR);
        cand = fmaxf(xx.y + bHx + rv * (hh.y + bHr), 0.0f);
        hn[2 * p + 1] = zv * hpv[2 * p + 1] + (1.0f - zv) * cand;
    }
    float* ho = hnext + (size_t)j * BB + bbase;
    *reinterpret_cast<float4*>(ho)     = make_float4(hn[0], hn[1], hn[2], hn[3]);
    *reinterpret_cast<float4*>(ho + 4) = make_float4(hn[4], hn[5], hn[6], hn[7]);
}

// ---------------------------------------------------------------------------
__global__ void __launch_bounds__(NTHR, 1) gru_persist(
    const float* __restrict__ xT,
    const float* __restrict__ W1, const float* __restrict__ U1,
    const float* __restrict__ bi1, const float* __restrict__ br1,
    const float* __restrict__ W2, const float* __restrict__ U2,
    const float* __restrict__ bi2, const float* __restrict__ br2,
    float* h1buf, float* h2buf, int* bars)
{
    extern __shared__ float smf[];
    float* sw1x = smf + OFF_W1X;
    float* su1  = smf + OFF_U1;
    float* sw2  = smf + OFF_W2;
    float* su2  = smf + OFF_U2;
    float* sact = smf + OFF_ACT;
    ull*   red  = (ull*)(smf + OFF_RED);

    const int tid  = threadIdx.x;
    const int cta  = blockIdx.x;
    const int ug   = cta >> 1, bh = cta & 1;
    const int bg   = tid & 7;
    const int unit = (tid >> 3) & 7;
    const int kg   = tid >> 6;
    const int slot = unit * 8 + bg;
    const int j    = ug * 8 + unit;
    const int bbase = bh * 64 + bg * 8;

    load_w(sw1x, W1, FF, ug, tid);
    load_w(su1,  U1, UU, ug, tid);
    load_w(sw2,  W2, UU, ug, tid);
    load_w(su2,  U2, UU, ug, tid);

    const float b1Z = bi1[j] + br1[j];
    const float b1R = bi1[UU + j] + br1[UU + j];
    const float b1Hx = bi1[2 * UU + j];
    const float b1Hr = br1[2 * UU + j];
    const float b2Z = bi2[j] + br2[j];
    const float b2R = bi2[UU + j] + br2[UU + j];
    const float b2Hx = bi2[2 * UU + j];
    const float b2Hr = br2[2 * UU + j];
    __syncthreads();

    bool pre = false;
    #pragma unroll 1
    for (int t = 0; t <= TT; t++) {
        const bool doL1 = (t < TT), doL2 = (t > 0);
        const float* xs    = xT    + (size_t)t * FF * BB;
        const float* h1rec = h1buf + (size_t)(t & 1) * (UU * BB);
        float*       h1nx  = h1buf + (size_t)((t + 1) & 1) * (UU * BB);
        const float* h2rec = h2buf + (size_t)((t + 1) & 1) * (UU * BB);  // H2[t-1]
        float*       h2nx  = h2buf + (size_t)(t & 1) * (UU * BB);        // H2[t]
        const int xch = doL1 ? FF / KC : 0;          // 4 (0 at tail)
        const int h1c = UU / KC;                     // 16
        const int h2c = doL2 ? UU / KC : 0;          // 16 (0 at t=0)
        const int nch = xch + h1c + h2c;             // 20 / 36 / 32 (all % 4 == 0)

        ull z1[4] = {0,0,0,0}, r1[4] = {0,0,0,0}, hx1[4] = {0,0,0,0}, hr1[4] = {0,0,0,0};
        ull z2[4] = {0,0,0,0}, r2[4] = {0,0,0,0}, hx2[4] = {0,0,0,0}, hr2[4] = {0,0,0,0};

        // chunk source resolver
        #define SRC(c) ((c) < xch ? xs + (size_t)(c) * KC * BB + bh * 64 \
                        : (c) < xch + h1c ? h1rec + (size_t)((c) - xch) * KC * BB + bh * 64 \
                        : h2rec + (size_t)((c) - xch - h1c) * KC * BB + bh * 64)

        // prologue (only when not prefetched pre-barrier): issue chunks 0,1,2
        if (!pre) {
            cp_chunk(sact + 0 * ABUF, SRC(0), tid);
            cp_chunk(sact + 1 * ABUF, SRC(1), tid);
            cp_chunk(sact + 2 * ABUF, SRC(2), tid);
        }

        #pragma unroll 1
        for (int ch = 0; ch < nch; ch++) {
            cp_wait2();                 // chunk ch complete (own thread's groups)
            __syncthreads();            // all threads' ch in; all done reading ch-1's buf
            if (ch + 3 < nch) cp_chunk(sact + ((ch + 3) & 3) * ABUF, SRC(ch + 3), tid);
            else              cp_commit_empty();   // keep group accounting uniform
            const float* A = sact + (ch & 3) * ABUF;
            if (ch < xch) {
                cc1(A, sw1x + ch * KC * 24, kg, unit, bg, z1, r1, hx1);
            } else if (ch < xch + h1c) {
                int r0 = (ch - xch) * KC * 24;
                if (doL1 && doL2) cc2(A, su1 + r0, sw2 + r0, kg, unit, bg, z1, r1, hr1, z2, r2, hx2);
                else if (doL1)    cc1(A, su1 + r0, kg, unit, bg, z1, r1, hr1);
                else              cc1(A, sw2 + r0, kg, unit, bg, z2, r2, hx2);
            } else {
                int r0 = (ch - xch - h1c) * KC * 24;
                cc1(A, su2 + r0, kg, unit, bg, z2, r2, hr2);
            }
        }
        #undef SRC

        // pre-barrier prefetch of next superstep's x chunks 0..2 (dependency-free).
        // Bufs 0..2 hold chunks nch-4..nch-2, already consumed by every thread's
        // own sequential loop by the time that thread issues these copies.
        const bool preNext = (t + 1 < TT);
        if (preNext) {
            const float* xn = xT + (size_t)(t + 1) * FF * BB + bh * 64;
            cp_chunk(sact + 0 * ABUF, xn, tid);
            cp_chunk(sact + 1 * ABUF, xn + (size_t)KC * BB, tid);
            cp_chunk(sact + 2 * ABUF, xn + (size_t)2 * KC * BB, tid);
        }

        // ---- phase 1: layer-1 k-split reduction + finalize ----
        if (doL1 && kg != 0)
            red_store(red + (size_t)(kg - 1) * 16 * 64 + slot, z1, r1, hx1, hr1);
        __syncthreads();
        if (doL1 && kg == 0) {
            red_accum(red, slot, z1, r1, hx1, hr1);
            finalize(h1rec, h1nx, j, bbase, z1, r1, hx1, hr1, b1Z, b1R, b1Hx, b1Hr);
        }
        __syncthreads();
        // ---- phase 2: layer-2 k-split reduction + finalize (same buffer) ----
        if (doL2 && kg != 1) {
            int s = (kg == 0) ? 0 : kg - 1;
            red_store(red + (size_t)s * 16 * 64 + slot, z2, r2, hx2, hr2);
        }
        __syncthreads();
        if (doL2 && kg == 1) {
            red_accum(red, slot, z2, r2, hx2, hr2);
            finalize(h2rec, h2nx, j, bbase, z2, r2, hx2, hr2, b2Z, b2R, b2Hx, b2Hr);
        }

        grid_barrier(&bars[t]);
        pre = preNext;
    }
}

// ---------------------------------------------------------------------------
__global__ void init_kernel(float* h1, float* h2, int* bars)
{
    int i = blockIdx.x * blockDim.x + threadIdx.x;
    if (i < 2 * UU * BB) { h1[i] = 0.0f; h2[i] = 0.0f; }
    if (i < TT + 2) bars[i] = 0;
}

// x (B, T, F) -> xT (T, F, B)
__global__ void transpose_x(const float* __restrict__ x, float* __restrict__ xT)
{
    __shared__ float tile[32][33];
    const int t  = blockIdx.x;
    const int bb = blockIdx.y * 32;
    const int ib = blockIdx.z * 32;
    const int tx = threadIdx.x, ty = threadIdx.y;  // 32 x 8

    #pragma unroll
    for (int r = 0; r < 4; r++)
        tile[ty + 8 * r][tx] = x[(size_t)(bb + ty + 8 * r) * TT * FF + (size_t)t * FF + ib + tx];
    __syncthreads();
    #pragma unroll
    for (int r = 0; r < 4; r++)
        xT[(size_t)t * FF * BB + (size_t)(ib + ty + 8 * r) * BB + bb + tx] = tile[tx][ty + 8 * r];
}

__global__ void head_kernel(const float* __restrict__ h,   // (U, B) final h2
                            const float* __restrict__ Wd,
                            const float* __restrict__ bd,
                            float* __restrict__ out)
{
    __shared__ float part[4][BB];
    int b = threadIdx.x & 127, q = threadIdx.x >> 7;
    float acc = 0.0f;
    #pragma unroll 8
    for (int k = q * 128; k < (q + 1) * 128; k++)
        acc += h[(size_t)k * BB + b] * __ldg(&Wd[k]);
    part[q][b] = acc;
    __syncthreads();
    if (q == 0)
        out[b] = part[0][b] + part[1][b] + part[2][b] + part[3][b] + bd[0];
}

// ---------------------------------------------------------------------------
extern "C" void kernel_launch(void* const* d_in, const int* in_sizes, int n_in,
                              void* d_out, int out_size)
{
    const float* x   = (const float*)d_in[0];
    const float* W1  = (const float*)d_in[1];
    const float* U1  = (const float*)d_in[2];
    const float* bi1 = (const float*)d_in[3];
    const float* br1 = (const float*)d_in[4];
    const float* W2  = (const float*)d_in[5];
    const float* U2  = (const float*)d_in[6];
    const float* bi2 = (const float*)d_in[7];
    const float* br2 = (const float*)d_in[8];
    const float* Wd  = (const float*)d_in[9];
    const float* bd  = (const float*)d_in[10];
    float* out = (float*)d_out;

    float *xT, *h1, *h2; int* bars;
    cudaGetSymbolAddress((void**)&xT,   g_xT);
    cudaGetSymbolAddress((void**)&h1,   g_h1);
    cudaGetSymbolAddress((void**)&h2,   g_h2);
    cudaGetSymbolAddress((void**)&bars, g_bar);

    cudaFuncSetAttribute(gru_persist, cudaFuncAttributeMaxDynamicSharedMemorySize,
                         SMEM_FLOATS * 4);

    init_kernel<<<(2 * UU * BB + 255) / 256, 256>>>(h1, h2, bars);
    transpose_x<<<dim3(TT, 4, 4), dim3(32, 8)>>>(x, xT);
    gru_persist<<<NCTA, NTHR, SMEM_FLOATS * 4>>>(
        xT, W1, U1, bi1, br1, W2, U2, bi2, br2, h1, h2, bars);
    // after tail superstep, final h2 lives in buffer 0
    head_kernel<<<1, 512>>>(h2, Wd, bd, out);
}

// round 7
// speedup vs baseline: 1.0589x; 1.0589x over previous
#include <cuda_runtime.h>
#include <cstdint>

typedef unsigned long long ull;

#define BB   128
#define TT   512
#define FF   128
#define UU   512
#define G3   1536
#define NCTA 128
#define NTHR 256
#define KC   64

#define AREG 516          // floats per bg region (KC*8 + 4 pad)
#define ABUF (8 * AREG)   // 4128 floats per act buffer

// SMEM float offsets
#define OFF_W1X 0          // 128*24  = 3072
#define OFF_U1  3072       // 512*24  = 12288
#define OFF_W2  15360      // 512*24  = 12288
#define OFF_U2  27648      // 512*24  = 12288
#define OFF_ACT 39936      // 2*4128  = 8256
#define OFF_RED 48192      // 3072 ull = 6144 floats (two-phase shared)
#define SMEM_FLOATS 54336  // 217344 bytes

// ---------------- static device scratch ----------------
__device__ __align__(128) float g_xT[(size_t)TT * FF * BB];  // (T, F, B)
__device__ __align__(128) float g_h1[2 * UU * BB];
__device__ __align__(128) float g_h2[2 * UU * BB];
__device__ __align__(128) int   g_bar[TT + 3];               // barrier slots 0..TT+1

// ---------------- helpers ----------------
__device__ __forceinline__ ull fma2(ull a, ull b, ull c) {
    ull d; asm("fma.rn.f32x2 %0, %1, %2, %3;" : "=l"(d) : "l"(a), "l"(b), "l"(c)); return d;
}
__device__ __forceinline__ ull add2(ull a, ull b) {
    ull d; asm("add.rn.f32x2 %0, %1, %2;" : "=l"(d) : "l"(a), "l"(b)); return d;
}
__device__ __forceinline__ ull pack2(float f) {
    ull d; asm("mov.b64 %0, {%1, %1};" : "=l"(d) : "f"(f)); return d;
}
__device__ __forceinline__ float2 asf2(ull v) {
    float2 f; asm("mov.b64 {%0, %1}, %2;" : "=f"(f.x), "=f"(f.y) : "l"(v)); return f;
}
__device__ __forceinline__ float sigm(float v) { return 1.0f / (1.0f + __expf(-v)); }

// R4-proven grid barrier + trailing-slot self-reset.
// Resetting slot s-1 at slot s is safe: passing s implies every CTA finished
// polling s-1. Slot TT+1 (the last) is reset at next-launch start instead.
__device__ __forceinline__ void grid_barrier(int* bars, int s) {
    __syncthreads();
    if (threadIdx.x == 0) {
        asm volatile("red.release.gpu.global.add.u32 [%0], 1;" :: "l"(bars + s) : "memory");
        int v;
        do {
            asm volatile("ld.acquire.gpu.global.u32 %0, [%1];" : "=r"(v) : "l"(bars + s) : "memory");
        } while (v < NCTA);
        if (s >= 1)
            asm volatile("st.global.relaxed.gpu.u32 [%0], %1;" :: "l"(bars + s - 1), "r"(0) : "memory");
    }
    __syncthreads();
}

// global weight slab -> smem [k][u*3+g], cols g*512 + ug*8 + u
__device__ void load_w(float* dst, const float* src, int R, int ug, int tid) {
    for (int idx = tid; idx < R * 24; idx += NTHR) {
        int k = idx / 24, c = idx - k * 24;
        int u = c / 3, g = c - u * 3;
        dst[idx] = src[(size_t)k * G3 + g * UU + ug * 8 + u];
    }
}

// stream one KC x 64-batch chunk: 4096 floats = 1024 float4 -> 4 per thread
__device__ __forceinline__ void cp_chunk(float* dstbuf, const float* src, int tid) {
    uint32_t d0 = (uint32_t)__cvta_generic_to_shared(dstbuf);
    #pragma unroll
    for (int i = 0; i < 4; i++) {
        int f = tid + NTHR * i;           // 0..1023
        int k = f >> 4, seg = f & 15;     // k: 0..63
        int bgr = seg >> 1, half = seg & 1;
        uint32_t da = d0 + (uint32_t)((bgr * AREG + k * 8 + half * 4) * 4);
        const float* s = src + (size_t)k * BB + seg * 4;
        asm volatile("cp.async.cg.shared.global [%0], [%1], 16;" :: "r"(da), "l"(s) : "memory");
    }
    asm volatile("cp.async.commit_group;" ::: "memory");
}
__device__ __forceinline__ void cp_wait0() {
    asm volatile("cp.async.wait_group 0;" ::: "memory");
}

// single-layer chunk: 12 FMA2 per k, KC/4 = 16 iters
__device__ __forceinline__ void cc1(const float* A, const float* w, int kg, int unit, int bg,
                                    ull* az, ull* ar, ull* ah) {
    #pragma unroll
    for (int i = 0; i < KC / 4; i++) {
        int k = 4 * i + kg;
        const float* ap = A + bg * AREG + k * 8;
        ulonglong2 p01 = *reinterpret_cast<const ulonglong2*>(ap);
        ulonglong2 p23 = *reinterpret_cast<const ulonglong2*>(ap + 4);
        const float* wp = w + k * 24 + unit * 3;
        ull wz = pack2(wp[0]), wr = pack2(wp[1]), wh = pack2(wp[2]);
        az[0] = fma2(p01.x, wz, az[0]); az[1] = fma2(p01.y, wz, az[1]);
        az[2] = fma2(p23.x, wz, az[2]); az[3] = fma2(p23.y, wz, az[3]);
        ar[0] = fma2(p01.x, wr, ar[0]); ar[1] = fma2(p01.y, wr, ar[1]);
        ar[2] = fma2(p23.x, wr, ar[2]); ar[3] = fma2(p23.y, wr, ar[3]);
        ah[0] = fma2(p01.x, wh, ah[0]); ah[1] = fma2(p01.y, wh, ah[1]);
        ah[2] = fma2(p23.x, wh, ah[2]); ah[3] = fma2(p23.y, wh, ah[3]);
    }
}

// dual-layer chunk over h1 rows: acts read once, 24 FMA2 per k
__device__ __forceinline__ void cc2(const float* A, const float* wa, const float* wb,
                                    int kg, int unit, int bg,
                                    ull* az1, ull* ar1, ull* ah1,
                                    ull* az2, ull* ar2, ull* ah2) {
    #pragma unroll
    for (int i = 0; i < KC / 4; i++) {
        int k = 4 * i + kg;
        const float* ap = A + bg * AREG + k * 8;
        ulonglong2 p01 = *reinterpret_cast<const ulonglong2*>(ap);
        ulonglong2 p23 = *reinterpret_cast<const ulonglong2*>(ap + 4);
        const float* wpa = wa + k * 24 + unit * 3;
        const float* wpb = wb + k * 24 + unit * 3;
        ull za = pack2(wpa[0]), ra = pack2(wpa[1]), ha = pack2(wpa[2]);
        ull zb = pack2(wpb[0]), rb = pack2(wpb[1]), hb = pack2(wpb[2]);
        az1[0] = fma2(p01.x, za, az1[0]); az1[1] = fma2(p01.y, za, az1[1]);
        az1[2] = fma2(p23.x, za, az1[2]); az1[3] = fma2(p23.y, za, az1[3]);
        ar1[0] = fma2(p01.x, ra, ar1[0]); ar1[1] = fma2(p01.y, ra, ar1[1]);
        ar1[2] = fma2(p23.x, ra, ar1[2]); ar1[3] = fma2(p23.y, ra, ar1[3]);
        ah1[0] = fma2(p01.x, ha, ah1[0]); ah1[1] = fma2(p01.y, ha, ah1[1]);
        ah1[2] = fma2(p23.x, ha, ah1[2]); ah1[3] = fma2(p23.y, ha, ah1[3]);
        az2[0] = fma2(p01.x, zb, az2[0]); az2[1] = fma2(p01.y, zb, az2[1]);
        az2[2] = fma2(p23.x, zb, az2[2]); az2[3] = fma2(p23.y, zb, az2[3]);
        ar2[0] = fma2(p01.x, rb, ar2[0]); ar2[1] = fma2(p01.y, rb, ar2[1]);
        ar2[2] = fma2(p23.x, rb, ar2[2]); ar2[3] = fma2(p23.y, rb, ar2[3]);
        ah2[0] = fma2(p01.x, hb, ah2[0]); ah2[1] = fma2(p01.y, hb, ah2[1]);
        ah2[2] = fma2(p23.x, hb, ah2[2]); ah2[3] = fma2(p23.y, hb, ah2[3]);
    }
}

__device__ __forceinline__ void red_store(ull* base, ull* z, ull* r, ull* hx, ull* hr) {
    #pragma unroll
    for (int p = 0; p < 4; p++) {
        base[p * 64]        = z[p];
        base[(4 + p) * 64]  = r[p];
        base[(8 + p) * 64]  = hx[p];
        base[(12 + p) * 64] = hr[p];
    }
}
__device__ __forceinline__ void red_accum(const ull* redb, int slot,
                                          ull* z, ull* r, ull* hx, ull* hr) {
    #pragma unroll
    for (int s = 0; s < 3; s++) {
        const ull* base = redb + (size_t)s * 16 * 64 + slot;
        #pragma unroll
        for (int p = 0; p < 4; p++) {
            z[p]  = add2(z[p],  base[p * 64]);
            r[p]  = add2(r[p],  base[(4 + p) * 64]);
            hx[p] = add2(hx[p], base[(8 + p) * 64]);
            hr[p] = add2(hr[p], base[(12 + p) * 64]);
        }
    }
}

__device__ __forceinline__ void finalize(const float* hprev, float* hnext,
                                         int j, int bbase,
                                         ull* z, ull* r, ull* hx, ull* hr,
                                         float bZ, float bR, float bHx, float bHr) {
    const float* hp = hprev + (size_t)j * BB + bbase;
    float4 h0 = __ldcg((const float4*)hp);
    float4 h1 = __ldcg((const float4*)(hp + 4));
    float hpv[8] = {h0.x, h0.y, h0.z, h0.w, h1.x, h1.y, h1.z, h1.w};
    float hn[8];
    #pragma unroll
    for (int p = 0; p < 4; p++) {
        float2 zz = asf2(z[p]), rr = asf2(r[p]), xx = asf2(hx[p]), hh = asf2(hr[p]);
        float zv = sigm(zz.x + bZ);
        float rv = sigm(rr.x + bR);
        float cand = fmaxf(xx.x + bHx + rv * (hh.x + bHr), 0.0f);
        hn[2 * p] = zv * hpv[2 * p] + (1.0f - zv) * cand;
        zv = sigm(zz.y + bZ);
        rv = sigm(rr.y + bR);
        cand = fmaxf(xx.y + bHx + rv * (hh.y + bHr), 0.0f);
        hn[2 * p + 1] = zv * hpv[2 * p + 1] + (1.0f - zv) * cand;
    }
    float* ho = hnext + (size_t)j * BB + bbase;
    *reinterpret_cast<float4*>(ho)     = make_float4(hn[0], hn[1], hn[2], hn[3]);
    *reinterpret_cast<float4*>(ho + 4) = make_float4(hn[4], hn[5], hn[6], hn[7]);
}

// ---------------------------------------------------------------------------
__global__ void __launch_bounds__(NTHR, 1) gru_persist(
    const float* __restrict__ xT,
    const float* __restrict__ W1, const float* __restrict__ U1,
    const float* __restrict__ bi1, const float* __restrict__ br1,
    const float* __restrict__ W2, const float* __restrict__ U2,
    const float* __restrict__ bi2, const float* __restrict__ br2,
    const float* __restrict__ Wd, const float* __restrict__ bd,
    float* h1buf, float* h2buf, int* bars, float* out)
{
    extern __shared__ float smf[];
    float* sw1x = smf + OFF_W1X;
    float* su1  = smf + OFF_U1;
    float* sw2  = smf + OFF_W2;
    float* su2  = smf + OFF_U2;
    float* sact = smf + OFF_ACT;
    ull*   red  = (ull*)(smf + OFF_RED);

    const int tid  = threadIdx.x;
    const int cta  = blockIdx.x;
    const int ug   = cta >> 1, bh = cta & 1;
    const int bg   = tid & 7;
    const int unit = (tid >> 3) & 7;
    const int kg   = tid >> 6;
    const int slot = unit * 8 + bg;
    const int j    = ug * 8 + unit;
    const int bbase = bh * 64 + bg * 8;

    // --- self-init: reset trailing barrier slot, zero own h slices ---
    if (tid == 0)
        asm volatile("st.global.relaxed.gpu.u32 [%0], %1;" :: "l"(bars + TT + 1), "r"(0) : "memory");
    {
        // zero h1buf[0] and h2buf[0] own (8 units x 64 batches) slice
        if (tid < 128) {
            int u = tid >> 4, f4 = tid & 15;
            float* p = h1buf + (size_t)(ug * 8 + u) * BB + bh * 64 + f4 * 4;
            *reinterpret_cast<float4*>(p) = make_float4(0.f, 0.f, 0.f, 0.f);
        } else {
            int t2 = tid - 128;
            int u = t2 >> 4, f4 = t2 & 15;
            float* p = h2buf + (size_t)(ug * 8 + u) * BB + bh * 64 + f4 * 4;
            *reinterpret_cast<float4*>(p) = make_float4(0.f, 0.f, 0.f, 0.f);
        }
    }

    load_w(sw1x, W1, FF, ug, tid);
    load_w(su1,  U1, UU, ug, tid);
    load_w(sw2,  W2, UU, ug, tid);
    load_w(su2,  U2, UU, ug, tid);

    const float b1Z = bi1[j] + br1[j];
    const float b1R = bi1[UU + j] + br1[UU + j];
    const float b1Hx = bi1[2 * UU + j];
    const float b1Hr = br1[2 * UU + j];
    const float b2Z = bi2[j] + br2[j];
    const float b2R = bi2[UU + j] + br2[UU + j];
    const float b2Hx = bi2[2 * UU + j];
    const float b2Hr = br2[2 * UU + j];

    // all CTAs' h zeroing + barrier reset visible before any cross-CTA reads
    grid_barrier(bars, 0);

    #pragma unroll 1
    for (int t = 0; t <= TT; t++) {
        const bool doL1 = (t < TT), doL2 = (t > 0);
        const float* xs    = xT    + (size_t)t * FF * BB;
        const float* h1rec = h1buf + (size_t)(t & 1) * (UU * BB);
        float*       h1nx  = h1buf + (size_t)((t + 1) & 1) * (UU * BB);
        const float* h2rec = h2buf + (size_t)((t + 1) & 1) * (UU * BB);  // H2[t-1]
        float*       h2nx  = h2buf + (size_t)(t & 1) * (UU * BB);        // H2[t]
        const int xch = doL1 ? FF / KC : 0;          // 2 (0 at tail)
        const int h1c = UU / KC;                     // 8
        const int h2c = doL2 ? UU / KC : 0;          // 8 (0 at t=0)
        const int nch = xch + h1c + h2c;             // 10 / 18 / 16

        ull z1[4] = {0,0,0,0}, r1[4] = {0,0,0,0}, hx1[4] = {0,0,0,0}, hr1[4] = {0,0,0,0};
        ull z2[4] = {0,0,0,0}, r2[4] = {0,0,0,0}, hx2[4] = {0,0,0,0}, hr2[4] = {0,0,0,0};

        #define SRC(c) ((c) < xch ? xs + (size_t)(c) * KC * BB + bh * 64 \
                        : (c) < xch + h1c ? h1rec + (size_t)((c) - xch) * KC * BB + bh * 64 \
                        : h2rec + (size_t)((c) - xch - h1c) * KC * BB + bh * 64)

        cp_chunk(sact, SRC(0), tid);   // prologue: chunk 0

        #pragma unroll 1
        for (int ch = 0; ch < nch; ch++) {
            cp_wait0();
            __syncthreads();            // chunk ch in for all; all done reading ch-1
            if (ch + 1 < nch)
                cp_chunk(sact + ((ch + 1) & 1) * ABUF, SRC(ch + 1), tid);
            const float* A = sact + (ch & 1) * ABUF;
            if (ch < xch) {
                cc1(A, sw1x + ch * KC * 24, kg, unit, bg, z1, r1, hx1);
            } else if (ch < xch + h1c) {
                int r0 = (ch - xch) * KC * 24;
                if (doL1 && doL2) cc2(A, su1 + r0, sw2 + r0, kg, unit, bg, z1, r1, hr1, z2, r2, hx2);
                else if (doL1)    cc1(A, su1 + r0, kg, unit, bg, z1, r1, hr1);
                else              cc1(A, sw2 + r0, kg, unit, bg, z2, r2, hx2);
            } else {
                int r0 = (ch - xch - h1c) * KC * 24;
                cc1(A, su2 + r0, kg, unit, bg, z2, r2, hr2);
            }
        }
        #undef SRC

        // ---- phase 1: layer-1 k-split reduction + finalize ----
        if (doL1 && kg != 0)
            red_store(red + (size_t)(kg - 1) * 16 * 64 + slot, z1, r1, hx1, hr1);
        __syncthreads();
        if (doL1 && kg == 0) {
            red_accum(red, slot, z1, r1, hx1, hr1);
            finalize(h1rec, h1nx, j, bbase, z1, r1, hx1, hr1, b1Z, b1R, b1Hx, b1Hr);
        }
        __syncthreads();
        // ---- phase 2: layer-2 k-split reduction + finalize ----
        if (doL2 && kg != 1) {
            int s = (kg == 0) ? 0 : kg - 1;
            red_store(red + (size_t)s * 16 * 64 + slot, z2, r2, hx2, hr2);
        }
        __syncthreads();
        if (doL2 && kg == 1) {
            red_accum(red, slot, z2, r2, hx2, hr2);
            finalize(h2rec, h2nx, j, bbase, z2, r2, hx2, hr2, b2Z, b2R, b2Hx, b2Hr);
        }

        grid_barrier(bars, 1 + t);
    }

    // ---- fused head: CTA0 computes out = h2_final^T Wd + bd ----
    if (cta == 0) {
        const float* h2fin = h2buf;          // buffer 0 after t=TT
        int b = tid & 127, half = tid >> 7;
        float acc = 0.0f;
        #pragma unroll 8
        for (int k = half * 256; k < half * 256 + 256; k++)
            acc += __ldcg(&h2fin[(size_t)k * BB + b]) * __ldg(&Wd[k]);
        if (half == 1) smf[b] = acc;
        __syncthreads();
        if (half == 0) out[b] = acc + smf[b] + bd[0];
    }
}

// ---------------------------------------------------------------------------
// x (B, T, F) -> xT (T, F, B)
__global__ void transpose_x(const float* __restrict__ x, float* __restrict__ xT)
{
    __shared__ float tile[32][33];
    const int t  = blockIdx.x;
    const int bb = blockIdx.y * 32;
    const int ib = blockIdx.z * 32;
    const int tx = threadIdx.x, ty = threadIdx.y;  // 32 x 8

    #pragma unroll
    for (int r = 0; r < 4; r++)
        tile[ty + 8 * r][tx] = x[(size_t)(bb + ty + 8 * r) * TT * FF + (size_t)t * FF + ib + tx];
    __syncthreads();
    #pragma unroll
    for (int r = 0; r < 4; r++)
        xT[(size_t)t * FF * BB + (size_t)(ib + ty + 8 * r) * BB + bb + tx] = tile[tx][ty + 8 * r];
}

// ---------------------------------------------------------------------------
extern "C" void kernel_launch(void* const* d_in, const int* in_sizes, int n_in,
                              void* d_out, int out_size)
{
    const float* x   = (const float*)d_in[0];
    const float* W1  = (const float*)d_in[1];
    const float* U1  = (const float*)d_in[2];
    const float* bi1 = (const float*)d_in[3];
    const float* br1 = (const float*)d_in[4];
    const float* W2  = (const float*)d_in[5];
    const float* U2  = (const float*)d_in[6];
    const float* bi2 = (const float*)d_in[7];
    const float* br2 = (const float*)d_in[8];
    const float* Wd  = (const float*)d_in[9];
    const float* bd  = (const float*)d_in[10];
    float* out = (float*)d_out;

    float *xT, *h1, *h2; int* bars;
    cudaGetSymbolAddress((void**)&xT,   g_xT);
    cudaGetSymbolAddress((void**)&h1,   g_h1);
    cudaGetSymbolAddress((void**)&h2,   g_h2);
    cudaGetSymbolAddress((void**)&bars, g_bar);

    cudaFuncSetAttribute(gru_persist, cudaFuncAttributeMaxDynamicSharedMemorySize,
                         SMEM_FLOATS * 4);

    transpose_x<<<dim3(TT, 4, 4), dim3(32, 8)>>>(x, xT);
    gru_persist<<<NCTA, NTHR, SMEM_FLOATS * 4>>>(
        xT, W1, U1, bi1, br1, W2, U2, bi2, br2, Wd, bd, h1, h2, bars, out);
}